// round 15
// baseline (speedup 1.0000x reference)
#include <cuda_runtime.h>
#include <math.h>

#define N0 8192
#define N1 4096
#define N2 8192
// W0: [N0, N1] row-major, W1: [N1, N2] row-major

#define GRID 152       // one block per SM, single wave
#define NTA 2048       // W0 tiles: 4 rows x 4096 cols = 64 KB
#define NTB 2048       // W1 tiles: 2 rows x 8192 cols = 64 KB

// Persistent state (device globals — allocation-free scratch)
__device__ float g_x1[N1];
__device__ float g_x2[N2];
__device__ float g_e1[N1];
__device__ float g_g1[N1];
__device__ float g_g2[N2];

__device__ __forceinline__ float dot4(float4 a, float4 b) {
    return a.x * b.x + a.y * b.y + a.z * b.z + a.w * b.w;
}

// ---------------------------------------------------------------------------
__global__ void k_init(float* __restrict__ out) {
    int i = blockIdx.x * blockDim.x + threadIdx.x;
    if (i < N1) { g_x1[i] = 0.f; g_g1[i] = 0.f; g_e1[i] = 0.f; }
    if (i < N2) { g_x2[i] = 0.f; g_g2[i] = 0.f; }
    if (i == 0) out[0] = 0.f;
}

// ---------------------------------------------------------------------------
// Step 1 specialized: x1 = x2 = 0 => e0 = x0, e1 = 0, g2 = 0.
// Only work: g1 = W0^T x0 (streaming axpy, no barriers).
// grid 256 x 512: block streams W0 rows [b*32, b*32+32) as 4 tiles x 8 rows.
// ---------------------------------------------------------------------------
__global__ void __launch_bounds__(512) k_step1(const float* __restrict__ x0,
                                               const float* __restrict__ W0) {
    const int tid = threadIdx.x;
    const int rowBase = blockIdx.x * 32;
    const float4* Wb = (const float4*)W0;
    float4 accA = make_float4(0, 0, 0, 0);
    float4 accB = make_float4(0, 0, 0, 0);

    #pragma unroll 1
    for (int t = 0; t < 4; t++) {
        const int rb = rowBase + t * 8;
        const float4* base = Wb + (size_t)rb * 1024 + tid;
        float4 wA[8], wB[8];
        #pragma unroll
        for (int r = 0; r < 8; r++) {
            wA[r] = base[(size_t)r * 1024];
            wB[r] = base[(size_t)r * 1024 + 512];
        }
        #pragma unroll
        for (int r = 0; r < 8; r++) {
            const float e = __ldg(x0 + rb + r);
            accA.x += e * wA[r].x;  accA.y += e * wA[r].y;
            accA.z += e * wA[r].z;  accA.w += e * wA[r].w;
            accB.x += e * wB[r].x;  accB.y += e * wB[r].y;
            accB.z += e * wB[r].z;  accB.w += e * wB[r].w;
        }
    }
    const int cA = 4 * tid;
    const int cB = 4 * (tid + 512);
    atomicAdd(&g_g1[cA + 0], accA.x);
    atomicAdd(&g_g1[cA + 1], accA.y);
    atomicAdd(&g_g1[cA + 2], accA.z);
    atomicAdd(&g_g1[cA + 3], accA.w);
    atomicAdd(&g_g1[cB + 0], accB.x);
    atomicAdd(&g_g1[cB + 1], accB.y);
    atomicAdd(&g_g1[cB + 2], accB.z);
    atomicAdd(&g_g1[cB + 3], accB.w);
}

// ---------------------------------------------------------------------------
// Fused step: double-buffered, single balanced wave (grid 152).
// Phase A: W0 tiles (4 rows, 2 float4/row/thread); block b owns tiles
//          [b*NTA/GRID, (b+1)*NTA/GRID) — 13 or 14 tiles.
// Phase B: W1 tiles (2 rows, 4 float4/row/thread); same partition.
// Next tile's 8 LDG.128 issue BEFORE the current tile's reduce/barriers.
// Column accumulators flushed once per phase via atomics.
// ---------------------------------------------------------------------------
__global__ void __launch_bounds__(512) k_step(const float* __restrict__ x0,
                                              const float* __restrict__ W0,
                                              const float* __restrict__ W1) {
    __shared__ float sp[4][16];
    __shared__ float se[4];
    const int tid  = threadIdx.x;
    const int warp = tid >> 5;
    const int lane = tid & 31;

    // ------------------ Phase A: W0 [8192 x 4096] ------------------
    {
        const int t0 = (int)(((long)blockIdx.x * NTA) / GRID);
        const int t1 = (int)(((long)(blockIdx.x + 1) * NTA) / GRID);
        const float4* Wb = (const float4*)W0;
        const float4* xv = (const float4*)g_x1;
        const float4 xA = xv[tid];
        const float4 xB = xv[tid + 512];
        float4 accA = make_float4(0, 0, 0, 0);
        float4 accB = make_float4(0, 0, 0, 0);

        float4 w[2][8];
        #pragma unroll
        for (int r = 0; r < 4; r++) {
            w[0][2*r]   = Wb[(size_t)(t0 * 4 + r) * 1024 + tid];
            w[0][2*r+1] = Wb[(size_t)(t0 * 4 + r) * 1024 + tid + 512];
        }
        #pragma unroll 1
        for (int t = t0; t < t1; t++) {
            const int cur = (t - t0) & 1, nxt = cur ^ 1;
            const int rb = t * 4;
            if (t + 1 < t1) {
                #pragma unroll
                for (int r = 0; r < 4; r++) {
                    w[nxt][2*r]   = Wb[(size_t)(rb + 4 + r) * 1024 + tid];
                    w[nxt][2*r+1] = Wb[(size_t)(rb + 4 + r) * 1024 + tid + 512];
                }
            }
            #pragma unroll
            for (int r = 0; r < 4; r++) {
                float p = dot4(w[cur][2*r], xA) + dot4(w[cur][2*r+1], xB);
                #pragma unroll
                for (int o = 16; o; o >>= 1) p += __shfl_xor_sync(0xFFFFFFFFu, p, o);
                if (lane == 0) sp[r][warp] = p;
            }
            __syncthreads();
            if (tid < 64) {
                const int r = tid >> 4, wi = tid & 15;
                float v = sp[r][wi];
                v += __shfl_xor_sync(0xFFFFFFFFu, v, 8);
                v += __shfl_xor_sync(0xFFFFFFFFu, v, 4);
                v += __shfl_xor_sync(0xFFFFFFFFu, v, 2);
                v += __shfl_xor_sync(0xFFFFFFFFu, v, 1);
                if (wi == 0) se[r] = __ldg(x0 + rb + r) - tanhf(v);
            }
            __syncthreads();
            #pragma unroll
            for (int r = 0; r < 4; r++) {
                const float e = se[r];
                accA.x += e * w[cur][2*r].x;    accA.y += e * w[cur][2*r].y;
                accA.z += e * w[cur][2*r].z;    accA.w += e * w[cur][2*r].w;
                accB.x += e * w[cur][2*r+1].x;  accB.y += e * w[cur][2*r+1].y;
                accB.z += e * w[cur][2*r+1].z;  accB.w += e * w[cur][2*r+1].w;
            }
        }
        const int cA = 4 * tid;
        const int cB = 4 * (tid + 512);
        atomicAdd(&g_g1[cA + 0], accA.x);
        atomicAdd(&g_g1[cA + 1], accA.y);
        atomicAdd(&g_g1[cA + 2], accA.z);
        atomicAdd(&g_g1[cA + 3], accA.w);
        atomicAdd(&g_g1[cB + 0], accB.x);
        atomicAdd(&g_g1[cB + 1], accB.y);
        atomicAdd(&g_g1[cB + 2], accB.z);
        atomicAdd(&g_g1[cB + 3], accB.w);
    }

    // ------------------ Phase B: W1 [4096 x 8192] ------------------
    {
        const int t0 = (int)(((long)blockIdx.x * NTB) / GRID);
        const int t1 = (int)(((long)(blockIdx.x + 1) * NTB) / GRID);
        const float4* Wb = (const float4*)W1;
        const float4* xv = (const float4*)g_x2;
        float4 xC[4];
        #pragma unroll
        for (int k = 0; k < 4; k++) xC[k] = xv[tid + k * 512];
        float4 acc[4] = {make_float4(0,0,0,0), make_float4(0,0,0,0),
                         make_float4(0,0,0,0), make_float4(0,0,0,0)};

        float4 w[2][8];
        #pragma unroll
        for (int r = 0; r < 2; r++)
            #pragma unroll
            for (int k = 0; k < 4; k++)
                w[0][4*r+k] = Wb[(size_t)(t0 * 2 + r) * 2048 + tid + k * 512];

        #pragma unroll 1
        for (int t = t0; t < t1; t++) {
            const int cur = (t - t0) & 1, nxt = cur ^ 1;
            const int rb = t * 2;
            if (t + 1 < t1) {
                #pragma unroll
                for (int r = 0; r < 2; r++)
                    #pragma unroll
                    for (int k = 0; k < 4; k++)
                        w[nxt][4*r+k] = Wb[(size_t)(rb + 2 + r) * 2048 + tid + k * 512];
            }
            #pragma unroll
            for (int r = 0; r < 2; r++) {
                float p = dot4(w[cur][4*r],   xC[0]) + dot4(w[cur][4*r+1], xC[1])
                        + dot4(w[cur][4*r+2], xC[2]) + dot4(w[cur][4*r+3], xC[3]);
                #pragma unroll
                for (int o = 16; o; o >>= 1) p += __shfl_xor_sync(0xFFFFFFFFu, p, o);
                if (lane == 0) sp[r][warp] = p;
            }
            __syncthreads();
            if (tid < 32) {
                const int r = tid >> 4, wi = tid & 15;
                float v = sp[r][wi];
                v += __shfl_xor_sync(0xFFFFFFFFu, v, 8);
                v += __shfl_xor_sync(0xFFFFFFFFu, v, 4);
                v += __shfl_xor_sync(0xFFFFFFFFu, v, 2);
                v += __shfl_xor_sync(0xFFFFFFFFu, v, 1);
                if (wi == 0) {
                    float e = g_x1[rb + r] - tanhf(v);
                    se[r] = e;
                    g_e1[rb + r] = e;
                }
            }
            __syncthreads();
            #pragma unroll
            for (int r = 0; r < 2; r++) {
                const float e = se[r];
                #pragma unroll
                for (int k = 0; k < 4; k++) {
                    acc[k].x += e * w[cur][4*r+k].x;
                    acc[k].y += e * w[cur][4*r+k].y;
                    acc[k].z += e * w[cur][4*r+k].z;
                    acc[k].w += e * w[cur][4*r+k].w;
                }
            }
        }
        #pragma unroll
        for (int k = 0; k < 4; k++) {
            const int c = 4 * (tid + k * 512);
            atomicAdd(&g_g2[c + 0], acc[k].x);
            atomicAdd(&g_g2[c + 1], acc[k].y);
            atomicAdd(&g_g2[c + 2], acc[k].z);
            atomicAdd(&g_g2[c + 3], acc[k].w);
        }
    }
}

// ---------------------------------------------------------------------------
// State update (separate kernel, 4.8 us measured). Zeroes grads for reuse.
// ---------------------------------------------------------------------------
__global__ void k_update() {
    int i = blockIdx.x * blockDim.x + threadIdx.x;
    if (i < N1) {
        float gr = fminf(fmaxf(-g_e1[i] + g_g1[i], -1.f), 1.f);
        g_x1[i] = tanhf(g_x1[i] + 0.01f * gr);
        g_g1[i] = 0.f;
    } else {
        int c = i - N1;
        float x2 = g_x2[c];
        float gr = fminf(fmaxf(-x2 + g_g2[c], -1.f), 1.f);
        g_x2[c] = tanhf(x2 + 0.01f * gr);
        g_g2[c] = 0.f;
    }
}

// ---------------------------------------------------------------------------
// Final step: err = ||x0 - tanh(W0@x1)||^2 + ||x1 - tanh(W1@x2)||^2 + ||x2||^2
// Warp-per-row; W0 rows fold in x2[j]^2 (N2 == N0).
// ---------------------------------------------------------------------------
__global__ void k_final(const float* __restrict__ x0,
                        const float* __restrict__ W0,
                        const float* __restrict__ W1,
                        float* __restrict__ out) {
    __shared__ float s_part[8];
    int warpInBlock = threadIdx.x >> 5;
    int warp = (blockIdx.x * blockDim.x + threadIdx.x) >> 5;
    int lane = threadIdx.x & 31;

    float local = 0.f;
    if (warp < N0) {
        const float4* row = (const float4*)(W0 + (size_t)warp * N1);
        const float4* xv  = (const float4*)g_x1;
        float acc = 0.f;
        #pragma unroll 4
        for (int i = lane; i < N1 / 4; i += 32) acc += dot4(row[i], xv[i]);
        #pragma unroll
        for (int o = 16; o; o >>= 1) acc += __shfl_xor_sync(0xFFFFFFFFu, acc, o);
        if (lane == 0) {
            float e = x0[warp] - tanhf(acc);
            float x2v = g_x2[warp];
            local = e * e + x2v * x2v;
        }
    } else {
        int r = warp - N0;
        const float4* row = (const float4*)(W1 + (size_t)r * N2);
        const float4* xv  = (const float4*)g_x2;
        float acc = 0.f;
        #pragma unroll 4
        for (int i = lane; i < N2 / 4; i += 32) acc += dot4(row[i], xv[i]);
        #pragma unroll
        for (int o = 16; o; o >>= 1) acc += __shfl_xor_sync(0xFFFFFFFFu, acc, o);
        if (lane == 0) {
            float e = g_x1[r] - tanhf(acc);
            local = e * e;
        }
    }

    if (lane == 0) s_part[warpInBlock] = local;
    __syncthreads();
    if (threadIdx.x == 0) {
        float s = 0.f;
        #pragma unroll
        for (int w = 0; w < 8; w++) s += s_part[w];
        atomicAdd(out, s);
    }
}

// ---------------------------------------------------------------------------
extern "C" void kernel_launch(void* const* d_in, const int* in_sizes, int n_in,
                              void* d_out, int out_size) {
    const float* x0 = (const float*)d_in[0];
    const float* W0 = (const float*)d_in[1];
    const float* W1 = (const float*)d_in[2];
    float* out = (float*)d_out;

    k_init<<<32, 256>>>(out);
    k_step1<<<256, 512>>>(x0, W0);                    // specialized step 1
    k_update<<<(N1 + N2) / 256, 256>>>();
    for (int s = 0; s < 8; s++) {
        k_step<<<GRID, 512>>>(x0, W0, W1);            // balanced + double-buffered
        k_update<<<(N1 + N2) / 256, 256>>>();
    }
    k_final<<<(N0 + N1) / 8, 256>>>(x0, W0, W1, out); // final error
}

// round 16
// speedup vs baseline: 1.5663x; 1.5663x over previous
#include <cuda_runtime.h>
#include <math.h>

#define N0 8192
#define N1 4096
#define N2 8192
// W0: [N0, N1] row-major, W1: [N1, N2] row-major

// Persistent state (device globals — allocation-free scratch)
__device__ float g_x1[N1];
__device__ float g_x2[N2];
__device__ float g_e1[N1];
__device__ float g_g1[N1];
__device__ float g_g2[N2];

__device__ __forceinline__ float dot4(float4 a, float4 b) {
    return a.x * b.x + a.y * b.y + a.z * b.z + a.w * b.w;
}

// ---------------------------------------------------------------------------
__global__ void k_init(float* __restrict__ out) {
    int i = blockIdx.x * blockDim.x + threadIdx.x;
    if (i < N1) { g_x1[i] = 0.f; g_g1[i] = 0.f; g_e1[i] = 0.f; }
    if (i < N2) { g_x2[i] = 0.f; g_g2[i] = 0.f; }
    if (i == 0) out[0] = 0.f;
}

// ---------------------------------------------------------------------------
// Step 1 specialized: x1 = x2 = 0 => e0 = x0, e1 = 0, g2 = 0.
// Only work: g1 = W0^T x0 (streaming axpy, no barriers).
// grid 256 x 512: block streams W0 rows [b*32, b*32+32) as 4 tiles x 8 rows.
// ---------------------------------------------------------------------------
__global__ void __launch_bounds__(512) k_step1(const float* __restrict__ x0,
                                               const float* __restrict__ W0) {
    const int tid = threadIdx.x;
    const int rowBase = blockIdx.x * 32;
    const float4* Wb = (const float4*)W0;
    float4 accA = make_float4(0, 0, 0, 0);
    float4 accB = make_float4(0, 0, 0, 0);

    #pragma unroll 1
    for (int t = 0; t < 4; t++) {
        const int rb = rowBase + t * 8;
        const float4* base = Wb + (size_t)rb * 1024 + tid;
        float4 wA[8], wB[8];
        #pragma unroll
        for (int r = 0; r < 8; r++) {
            wA[r] = base[(size_t)r * 1024];
            wB[r] = base[(size_t)r * 1024 + 512];
        }
        #pragma unroll
        for (int r = 0; r < 8; r++) {
            const float e = __ldg(x0 + rb + r);
            accA.x += e * wA[r].x;  accA.y += e * wA[r].y;
            accA.z += e * wA[r].z;  accA.w += e * wA[r].w;
            accB.x += e * wB[r].x;  accB.y += e * wB[r].y;
            accB.z += e * wB[r].z;  accB.w += e * wB[r].w;
        }
    }
    const int cA = 4 * tid;
    const int cB = 4 * (tid + 512);
    atomicAdd(&g_g1[cA + 0], accA.x);
    atomicAdd(&g_g1[cA + 1], accA.y);
    atomicAdd(&g_g1[cA + 2], accA.z);
    atomicAdd(&g_g1[cA + 3], accA.w);
    atomicAdd(&g_g1[cB + 0], accB.x);
    atomicAdd(&g_g1[cB + 1], accB.y);
    atomicAdd(&g_g1[cB + 2], accB.z);
    atomicAdd(&g_g1[cB + 3], accB.w);
}

// ---------------------------------------------------------------------------
// Fused step: grid 256 split (champion) + round-10 double-buffer with
// COMPILE-TIME trip counts (16 tiles, unroll 2 -> cur/nxt are constants,
// w[2][8] stays in registers — regs ~118, no local spill).
// Blocks [0,128): W0, 64 rows = 16 tiles x 4 rows (2 float4/row/thread).
// Blocks [128,256): W1, 32 rows = 16 tiles x 2 rows (4 float4/row/thread).
// ---------------------------------------------------------------------------
__global__ void __launch_bounds__(512) k_step(const float* __restrict__ x0,
                                              const float* __restrict__ W0,
                                              const float* __restrict__ W1) {
    __shared__ float sp[4][16];
    __shared__ float se[4];
    const int tid  = threadIdx.x;
    const int warp = tid >> 5;
    const int lane = tid & 31;

    if (blockIdx.x < 128) {
        // ---------------- W0 half: [8192 x 4096] ----------------
        const int rowBase = blockIdx.x * 64;
        const float4* Wb = (const float4*)W0;
        const float4* xv = (const float4*)g_x1;
        const float4 xA = xv[tid];
        const float4 xB = xv[tid + 512];
        float4 accA = make_float4(0, 0, 0, 0);
        float4 accB = make_float4(0, 0, 0, 0);

        float4 w[2][8];
        #pragma unroll
        for (int r = 0; r < 4; r++) {
            w[0][2*r]   = Wb[(size_t)(rowBase + r) * 1024 + tid];
            w[0][2*r+1] = Wb[(size_t)(rowBase + r) * 1024 + tid + 512];
        }
        #pragma unroll 2
        for (int t = 0; t < 16; t++) {
            const int cur = t & 1, nxt = cur ^ 1;
            const int rb = rowBase + t * 4;
            if (t < 15) {
                #pragma unroll
                for (int r = 0; r < 4; r++) {
                    w[nxt][2*r]   = Wb[(size_t)(rb + 4 + r) * 1024 + tid];
                    w[nxt][2*r+1] = Wb[(size_t)(rb + 4 + r) * 1024 + tid + 512];
                }
            }
            #pragma unroll
            for (int r = 0; r < 4; r++) {
                float p = dot4(w[cur][2*r], xA) + dot4(w[cur][2*r+1], xB);
                #pragma unroll
                for (int o = 16; o; o >>= 1) p += __shfl_xor_sync(0xFFFFFFFFu, p, o);
                if (lane == 0) sp[r][warp] = p;
            }
            __syncthreads();
            if (tid < 64) {
                const int r = tid >> 4, wi = tid & 15;
                float v = sp[r][wi];
                v += __shfl_xor_sync(0xFFFFFFFFu, v, 8);
                v += __shfl_xor_sync(0xFFFFFFFFu, v, 4);
                v += __shfl_xor_sync(0xFFFFFFFFu, v, 2);
                v += __shfl_xor_sync(0xFFFFFFFFu, v, 1);
                if (wi == 0) se[r] = __ldg(x0 + rb + r) - tanhf(v);
            }
            __syncthreads();
            #pragma unroll
            for (int r = 0; r < 4; r++) {
                const float e = se[r];
                accA.x += e * w[cur][2*r].x;    accA.y += e * w[cur][2*r].y;
                accA.z += e * w[cur][2*r].z;    accA.w += e * w[cur][2*r].w;
                accB.x += e * w[cur][2*r+1].x;  accB.y += e * w[cur][2*r+1].y;
                accB.z += e * w[cur][2*r+1].z;  accB.w += e * w[cur][2*r+1].w;
            }
        }
        const int cA = 4 * tid;
        const int cB = 4 * (tid + 512);
        atomicAdd(&g_g1[cA + 0], accA.x);
        atomicAdd(&g_g1[cA + 1], accA.y);
        atomicAdd(&g_g1[cA + 2], accA.z);
        atomicAdd(&g_g1[cA + 3], accA.w);
        atomicAdd(&g_g1[cB + 0], accB.x);
        atomicAdd(&g_g1[cB + 1], accB.y);
        atomicAdd(&g_g1[cB + 2], accB.z);
        atomicAdd(&g_g1[cB + 3], accB.w);
    } else {
        // ---------------- W1 half: [4096 x 8192] ----------------
        const int rowBase = (blockIdx.x - 128) * 32;
        const float4* Wb = (const float4*)W1;
        const float4* xv = (const float4*)g_x2;
        float4 xC[4];
        #pragma unroll
        for (int k = 0; k < 4; k++) xC[k] = xv[tid + k * 512];
        float4 acc[4] = {make_float4(0,0,0,0), make_float4(0,0,0,0),
                         make_float4(0,0,0,0), make_float4(0,0,0,0)};

        float4 w[2][8];
        #pragma unroll
        for (int r = 0; r < 2; r++)
            #pragma unroll
            for (int k = 0; k < 4; k++)
                w[0][4*r+k] = Wb[(size_t)(rowBase + r) * 2048 + tid + k * 512];

        #pragma unroll 2
        for (int t = 0; t < 16; t++) {
            const int cur = t & 1, nxt = cur ^ 1;
            const int rb = rowBase + t * 2;
            if (t < 15) {
                #pragma unroll
                for (int r = 0; r < 2; r++)
                    #pragma unroll
                    for (int k = 0; k < 4; k++)
                        w[nxt][4*r+k] = Wb[(size_t)(rb + 2 + r) * 2048 + tid + k * 512];
            }
            #pragma unroll
            for (int r = 0; r < 2; r++) {
                float p = dot4(w[cur][4*r],   xC[0]) + dot4(w[cur][4*r+1], xC[1])
                        + dot4(w[cur][4*r+2], xC[2]) + dot4(w[cur][4*r+3], xC[3]);
                #pragma unroll
                for (int o = 16; o; o >>= 1) p += __shfl_xor_sync(0xFFFFFFFFu, p, o);
                if (lane == 0) sp[r][warp] = p;
            }
            __syncthreads();
            if (tid < 32) {
                const int r = tid >> 4, wi = tid & 15;
                float v = sp[r][wi];
                v += __shfl_xor_sync(0xFFFFFFFFu, v, 8);
                v += __shfl_xor_sync(0xFFFFFFFFu, v, 4);
                v += __shfl_xor_sync(0xFFFFFFFFu, v, 2);
                v += __shfl_xor_sync(0xFFFFFFFFu, v, 1);
                if (wi == 0) {
                    float e = g_x1[rb + r] - tanhf(v);
                    se[r] = e;
                    g_e1[rb + r] = e;
                }
            }
            __syncthreads();
            #pragma unroll
            for (int r = 0; r < 2; r++) {
                const float e = se[r];
                #pragma unroll
                for (int k = 0; k < 4; k++) {
                    acc[k].x += e * w[cur][4*r+k].x;
                    acc[k].y += e * w[cur][4*r+k].y;
                    acc[k].z += e * w[cur][4*r+k].z;
                    acc[k].w += e * w[cur][4*r+k].w;
                }
            }
        }
        #pragma unroll
        for (int k = 0; k < 4; k++) {
            const int c = 4 * (tid + k * 512);
            atomicAdd(&g_g2[c + 0], acc[k].x);
            atomicAdd(&g_g2[c + 1], acc[k].y);
            atomicAdd(&g_g2[c + 2], acc[k].z);
            atomicAdd(&g_g2[c + 3], acc[k].w);
        }
    }
}

// ---------------------------------------------------------------------------
// State update (separate kernel, 4.8 us measured). Zeroes grads for reuse.
// ---------------------------------------------------------------------------
__global__ void k_update() {
    int i = blockIdx.x * blockDim.x + threadIdx.x;
    if (i < N1) {
        float gr = fminf(fmaxf(-g_e1[i] + g_g1[i], -1.f), 1.f);
        g_x1[i] = tanhf(g_x1[i] + 0.01f * gr);
        g_g1[i] = 0.f;
    } else {
        int c = i - N1;
        float x2 = g_x2[c];
        float gr = fminf(fmaxf(-x2 + g_g2[c], -1.f), 1.f);
        g_x2[c] = tanhf(x2 + 0.01f * gr);
        g_g2[c] = 0.f;
    }
}

// ---------------------------------------------------------------------------
// Final step: err = ||x0 - tanh(W0@x1)||^2 + ||x1 - tanh(W1@x2)||^2 + ||x2||^2
// Warp-per-row; W0 rows fold in x2[j]^2 (N2 == N0).
// ---------------------------------------------------------------------------
__global__ void k_final(const float* __restrict__ x0,
                        const float* __restrict__ W0,
                        const float* __restrict__ W1,
                        float* __restrict__ out) {
    __shared__ float s_part[8];
    int warpInBlock = threadIdx.x >> 5;
    int warp = (blockIdx.x * blockDim.x + threadIdx.x) >> 5;
    int lane = threadIdx.x & 31;

    float local = 0.f;
    if (warp < N0) {
        const float4* row = (const float4*)(W0 + (size_t)warp * N1);
        const float4* xv  = (const float4*)g_x1;
        float acc = 0.f;
        #pragma unroll 4
        for (int i = lane; i < N1 / 4; i += 32) acc += dot4(row[i], xv[i]);
        #pragma unroll
        for (int o = 16; o; o >>= 1) acc += __shfl_xor_sync(0xFFFFFFFFu, acc, o);
        if (lane == 0) {
            float e = x0[warp] - tanhf(acc);
            float x2v = g_x2[warp];
            local = e * e + x2v * x2v;
        }
    } else {
        int r = warp - N0;
        const float4* row = (const float4*)(W1 + (size_t)r * N2);
        const float4* xv  = (const float4*)g_x2;
        float acc = 0.f;
        #pragma unroll 4
        for (int i = lane; i < N2 / 4; i += 32) acc += dot4(row[i], xv[i]);
        #pragma unroll
        for (int o = 16; o; o >>= 1) acc += __shfl_xor_sync(0xFFFFFFFFu, acc, o);
        if (lane == 0) {
            float e = g_x1[r] - tanhf(acc);
            local = e * e;
        }
    }

    if (lane == 0) s_part[warpInBlock] = local;
    __syncthreads();
    if (threadIdx.x == 0) {
        float s = 0.f;
        #pragma unroll
        for (int w = 0; w < 8; w++) s += s_part[w];
        atomicAdd(out, s);
    }
}

// ---------------------------------------------------------------------------
extern "C" void kernel_launch(void* const* d_in, const int* in_sizes, int n_in,
                              void* d_out, int out_size) {
    const float* x0 = (const float*)d_in[0];
    const float* W0 = (const float*)d_in[1];
    const float* W1 = (const float*)d_in[2];
    float* out = (float*)d_out;

    k_init<<<32, 256>>>(out);
    k_step1<<<256, 512>>>(x0, W0);                    // specialized step 1
    k_update<<<(N1 + N2) / 256, 256>>>();
    for (int s = 0; s < 8; s++) {
        k_step<<<256, 512>>>(x0, W0, W1);             // double-buffered engine
        k_update<<<(N1 + N2) / 256, 256>>>();
    }
    k_final<<<(N0 + N1) / 8, 256>>>(x0, W0, W1, out); // final error
}